// round 16
// baseline (speedup 1.0000x reference)
#include <cuda_runtime.h>
#include <cuda_bf16.h>
#include <math.h>

#define BQ 8
#define NTOK 256
#define HH 8
#define CC 32
#define INNER 128
#define NWIN 512
#define NTOKENS (BQ*128*128)

__device__ float    g_xres[(size_t)NTOKENS*CC];
__device__ unsigned g_y1[(size_t)NTOKENS*64];
// packed weights (zero-init pads)
__device__ unsigned g_pw_qkv[8*16*104];
__device__ unsigned g_pw_rev[128*40];
__device__ unsigned g_pw_w1[16*136];
__device__ unsigned g_pw_w2[64*40];
__device__ unsigned g_pw_cw[9*64*128];
__device__ float    g_rpbp[8*964];    // pre-scaled by log2(e)

__device__ __forceinline__ float gelu_exact(float x) {
    return 0.5f * x * (1.0f + erff(x * 0.70710678118654752440f));
}
__device__ __forceinline__ float ex2(float x) {
    float r; asm("ex2.approx.f32 %0, %1;" : "=f"(r) : "f"(x));
    return r;
}
__device__ __forceinline__ unsigned pk(float a, float b) {
    __nv_bfloat162 t = __floats2bfloat162_rn(a, b);
    return *reinterpret_cast<unsigned*>(&t);
}
__device__ __forceinline__ void mma_bf16(float* c, const unsigned* a, const unsigned* b) {
    asm volatile("mma.sync.aligned.m16n8k16.row.col.f32.bf16.bf16.f32 "
        "{%0,%1,%2,%3},{%4,%5,%6,%7},{%8,%9},{%0,%1,%2,%3};"
        : "+f"(c[0]), "+f"(c[1]), "+f"(c[2]), "+f"(c[3])
        : "r"(a[0]), "r"(a[1]), "r"(a[2]), "r"(a[3]), "r"(b[0]), "r"(b[1]));
}
__device__ __forceinline__ void cpa16(void* dst, const void* src) {
    unsigned d = (unsigned)__cvta_generic_to_shared(dst);
    asm volatile("cp.async.cg.shared.global [%0], [%1], 16;" :: "r"(d), "l"(src));
}
__device__ __forceinline__ void cpa16z(void* dst, const void* src, int sz) {
    unsigned d = (unsigned)__cvta_generic_to_shared(dst);
    asm volatile("cp.async.cg.shared.global [%0], [%1], 16, %2;" :: "r"(d), "l"(src), "r"(sz));
}
#define CPA_COMMIT asm volatile("cp.async.commit_group;" ::: "memory")
#define CPA_WAIT0  asm volatile("cp.async.wait_group 0;" ::: "memory")

// ============ K0: one-time weight packing ================================
__global__ void k_pack(const float* __restrict__ qkvw, const float* __restrict__ revw,
                       const float* __restrict__ w1, const float* __restrict__ w2,
                       const float* __restrict__ cw, const float* __restrict__ rpbt) {
    int i = blockIdx.x * 256 + threadIdx.x;
    if (i < 73728) {
        int tap = i >> 13, r = i & 8191;
        int c2 = r >> 7, co = r & 127;
        g_pw_cw[i] = pk(cw[((size_t)tap*128 + 2*c2)*128 + co],
                        cw[((size_t)tap*128 + 2*c2 + 1)*128 + co]);
    }
    if (i < 12288) {
        int hh = i / 1536, r = i % 1536;
        int c2 = r / 96, col = r % 96;
        int gcol = (col >> 5)*256 + hh*32 + (col & 31);
        g_pw_qkv[(hh*16 + c2)*104 + col] = pk(qkvw[2*c2*768 + gcol], qkvw[(2*c2+1)*768 + gcol]);
    }
    if (i < 7712) {
        int hh = i / 964, j = i % 964;
        g_rpbp[hh*964 + j] = (j < 961) ? rpbt[j*8 + hh] * 1.4426950408889634f : 0.f;
    }
    if (i < 4096) {
        int k2 = i >> 5, n = i & 31;
        g_pw_rev[k2*40 + n] = pk(revw[2*k2*32 + n], revw[(2*k2+1)*32 + n]);
    }
    if (i < 2048) {
        int c2 = i >> 7, n = i & 127;
        g_pw_w1[c2*136 + n] = pk(w1[2*c2*128 + n], w1[(2*c2+1)*128 + n]);
    }
    if (i < 2048) {
        int k2 = i >> 5, n = i & 31;
        g_pw_w2[k2*40 + n] = pk(w2[2*k2*32 + n], w2[(2*k2+1)*32 + n]);
    }
}

// ============ K2: window megakernel: LN1 + QKV + attn(8h) + rev + LN2 + lp1
#define ATTN_SMEM (23144*4)
__global__ void __launch_bounds__(256,2) k_attn(const float* __restrict__ x,
        const float* __restrict__ n1g, const float* __restrict__ n1b,
        const float* __restrict__ modw,
        const float* __restrict__ qkvb, const float* __restrict__ revb,
        const float* __restrict__ n2g, const float* __restrict__ n2b,
        const float* __restrict__ bb1) {
    extern __shared__ unsigned smu[];
    unsigned* sh_kT  = smu;                 // 4224 (start: sh_h overlay; end: sh_a)
    unsigned* sh_v   = smu + 4224;          // 5120
    unsigned* sh_wq  = smu + 9344;          // 2x1664 double buffer
    unsigned* sh_rev = smu + 12672;         // 5120
    unsigned* sh_w1  = smu + 17792;         // 2176
    float* sh_rpb    = (float*)(smu + 19968);  // 2x964 double buffer
    int*   sh_meta   = (int*)(smu + 21896);    // 256
    float* sh_ball   = (float*)(smu + 22152);  // 768
    float* sh_f      = (float*)(smu + 22920);  // 224

    int w = blockIdx.x;
    int tid = threadIdx.x, lane = tid & 31, warp = tid >> 5;
    int tg = lane >> 2, tq = lane & 3;
    int qb = warp * 32;
    bool uni = (((w & 63) >> 3) < 7) && ((w & 7) < 7);

    // ---- one-time staging via cp.async (pure copies) ----
    for (int j = tid; j < 1280; j += 256) cpa16((uint4*)sh_rev + j, (const uint4*)g_pw_rev + j);
    for (int j = tid; j < 544; j += 256)  cpa16((uint4*)sh_w1 + j, (const uint4*)g_pw_w1 + j);
    for (int j = tid; j < 416; j += 256)  cpa16((uint4*)sh_wq + j, (const uint4*)g_pw_qkv + j);
    for (int j = tid; j < 241; j += 256)  cpa16((uint4*)sh_rpb + j, (const uint4*)g_rpbp + j);
    CPA_COMMIT;
    for (int j = tid; j < 768; j += 256)  sh_ball[j] = qkvb[j];
    if (tid < 32) { sh_f[tid] = revb[tid]; sh_f[32+tid] = n2g[tid]; sh_f[64+tid] = n2b[tid]; }
    if (tid < 128) sh_f[96+tid] = bb1[tid];
    {
        int n = tid, ww = w & 63;
        int ry = (ww>>3)*16 + (n>>4), rx = (ww&7)*16 + (n&15);
        int hr = ry < 112 ? 0 : (ry < 120 ? 1 : 2);
        int wr = rx < 112 ? 0 : (rx < 120 ? 1 : 2);
        sh_meta[n] = ((n>>4)*31 + (n&15)) | ((hr*3+wr) << 16);
    }

    // ---- LN1 + shift + modulator -> sh_h (transient overlay on kT) ----
    unsigned* sh_h = sh_kT;
    {
        int n = tid, b = w >> 6, ww = w & 63;
        int ry = (ww>>3)*16 + (n>>4), rx = (ww&7)*16 + (n&15);
        int y = (ry + 8) & 127, xx = (rx + 8) & 127;
        const float* xp = x + ((size_t)b*16384 + (size_t)y*128 + xx)*CC;
        float v[CC];
#pragma unroll
        for (int i = 0; i < 8; i++) {
            float4 t = ((const float4*)xp)[i];
            v[4*i]=t.x; v[4*i+1]=t.y; v[4*i+2]=t.z; v[4*i+3]=t.w;
        }
        float mean = 0.f;
#pragma unroll
        for (int c = 0; c < CC; c++) mean += v[c];
        mean *= (1.0f/CC);
        float var = 0.f;
#pragma unroll
        for (int c = 0; c < CC; c++) { float d = v[c]-mean; var += d*d; }
        float rstd = rsqrtf(var*(1.0f/CC) + 1e-5f);
        const float4* mp = (const float4*)(modw + n*CC);
#pragma unroll
        for (int i = 0; i < 8; i++) {
            float4 m = mp[i];
            int c = 4*i;
            sh_h[n*20 + 2*i]   = pk((v[c+0]-mean)*rstd*n1g[c+0]+n1b[c+0]+m.x,
                                    (v[c+1]-mean)*rstd*n1g[c+1]+n1b[c+1]+m.y);
            sh_h[n*20 + 2*i+1] = pk((v[c+2]-mean)*rstd*n1g[c+2]+n1b[c+2]+m.z,
                                    (v[c+3]-mean)*rstd*n1g[c+3]+n1b[c+3]+m.w);
        }
    }
    CPA_WAIT0;
    __syncthreads();

    unsigned ha[2][8];
#pragma unroll
    for (int mt = 0; mt < 2; mt++) {
        int r = qb + mt*16 + tg;
        ha[mt][0]=sh_h[r*20+tq];        ha[mt][1]=sh_h[(r+8)*20+tq];
        ha[mt][2]=sh_h[r*20+tq+4];      ha[mt][3]=sh_h[(r+8)*20+tq+4];
        ha[mt][4]=sh_h[r*20+tq+8];      ha[mt][5]=sh_h[(r+8)*20+tq+8];
        ha[mt][6]=sh_h[r*20+tq+12];     ha[mt][7]=sh_h[(r+8)*20+tq+12];
    }
    int rb[2][2], rid[2][2];
#pragma unroll
    for (int mt=0; mt<2; mt++)
#pragma unroll
        for (int h=0; h<2; h++) {
            int q = qb + mt*16 + tg + 8*h;
            rb[mt][h] = ((q>>4)+15)*31 + ((q&15)+15);
            rid[mt][h] = sh_meta[q] >> 16;
        }
    __syncthreads();

    float acc_rev[2][4][4];
#pragma unroll
    for (int mt=0; mt<2; mt++)
#pragma unroll
        for (int nt=0; nt<4; nt++)
#pragma unroll
            for (int r=0; r<4; r++) acc_rev[mt][nt][r] = 0.f;

    // ================= head loop =================
    for (int hh = 0; hh < 8; hh++) {
        int p = hh & 1;
        const unsigned* wqp = sh_wq + p*1664;
        const float* rpbp = sh_rpb + p*964;

        unsigned qrl[2][4], qrh[2][4];
        __nv_bfloat16* vb = (__nv_bfloat16*)sh_v;
#pragma unroll
        for (int sec = 0; sec < 3; sec++) {
            float acc[2][4][4];
#pragma unroll
            for (int mt=0; mt<2; mt++)
#pragma unroll
                for (int nt=0; nt<4; nt++)
#pragma unroll
                    for (int r=0; r<4; r++) acc[mt][nt][r] = 0.f;
#pragma unroll
            for (int ks = 0; ks < 2; ks++) {
#pragma unroll
                for (int nt=0; nt<4; nt++) {
                    unsigned B[2];
                    B[0]=wqp[(8*ks+tq)*104 + sec*32 + nt*8+tg];
                    B[1]=wqp[(8*ks+tq+4)*104 + sec*32 + nt*8+tg];
                    mma_bf16(acc[0][nt], &ha[0][ks*4], B);
                    mma_bf16(acc[1][nt], &ha[1][ks*4], B);
                }
            }
#pragma unroll
            for (int mt=0; mt<2; mt++)
#pragma unroll
            for (int nt=0; nt<4; nt++) {
                int col = nt*8 + 2*tq;
                int r0 = qb + mt*16 + tg;
                float bb0 = sh_ball[sec*256 + hh*32 + col];
                float bb1v = sh_ball[sec*256 + hh*32 + col + 1];
                float v0=acc[mt][nt][0]+bb0, v1=acc[mt][nt][1]+bb1v;
                float v2=acc[mt][nt][2]+bb0, v3=acc[mt][nt][3]+bb1v;
                if (sec == 0) {
                    const float SC = 0.25508694038098612f;  // 1/sqrt(32)*log2(e)
                    qrl[mt][nt] = pk(v0*SC, v1*SC);
                    qrh[mt][nt] = pk(v2*SC, v3*SC);
                } else if (sec == 1) {
                    sh_kT[(col>>1)*264 + r0]   = pk(v0, v1);
                    sh_kT[(col>>1)*264 + r0+8] = pk(v2, v3);
                } else {
                    int r1 = r0 + 8, par = r0 & 1;
                    vb[(r0>>1)*80 + col*2     + par] = __float2bfloat16(v0);
                    vb[(r0>>1)*80 + (col+1)*2 + par] = __float2bfloat16(v1);
                    vb[(r1>>1)*80 + col*2     + par] = __float2bfloat16(v2);
                    vb[(r1>>1)*80 + (col+1)*2 + par] = __float2bfloat16(v3);
                }
            }
        }
        // ---- prefetch next head (async; completes during flash+rev) ----
        if (hh < 7) {
            const uint4* src = (const uint4*)(g_pw_qkv + (hh+1)*1664);
            uint4* dst = (uint4*)(sh_wq + (1-p)*1664);
            for (int j = tid; j < 416; j += 256) cpa16(dst + j, src + j);
            const uint4* rs = (const uint4*)(g_rpbp + (hh+1)*964);
            uint4* rd = (uint4*)(sh_rpb + (1-p)*964);
            for (int j = tid; j < 241; j += 256) cpa16(rd + j, rs + j);
            CPA_COMMIT;
        }
        __syncthreads();   // kT/V visible

        float psL[2] = {0.f,0.f}, psH[2] = {0.f,0.f};
        float o[2][4][4];
#pragma unroll
        for (int mt=0; mt<2; mt++)
#pragma unroll
            for (int nt=0; nt<4; nt++)
#pragma unroll
                for (int r=0; r<4; r++) o[mt][nt][r] = 0.f;

        for (int kc = 0; kc < 8; kc++) {
            int kb = kc * 32;
            float s[2][4][4];
#pragma unroll
            for (int mt=0; mt<2; mt++)
#pragma unroll
                for (int nt=0; nt<4; nt++)
#pragma unroll
                    for (int r=0; r<4; r++) s[mt][nt][r] = 0.f;
#pragma unroll
            for (int ks = 0; ks < 2; ks++) {
                unsigned A0[4] = {qrl[0][2*ks], qrh[0][2*ks], qrl[0][2*ks+1], qrh[0][2*ks+1]};
                unsigned A1[4] = {qrl[1][2*ks], qrh[1][2*ks], qrl[1][2*ks+1], qrh[1][2*ks+1]};
#pragma unroll
                for (int nt=0; nt<4; nt++) {
                    unsigned B[2];
                    int key = kb + nt*8 + tg;
                    B[0]=sh_kT[(8*ks+tq)*264 + key];
                    B[1]=sh_kT[(8*ks+tq+4)*264 + key];
                    mma_bf16(s[0][nt], A0, B);
                    mma_bf16(s[1][nt], A1, B);
                }
            }
            unsigned pl[2][4], ph[2][4];
            if (uni) {
#pragma unroll
                for (int nt=0; nt<4; nt++) {
                    int k0i = kb + nt*8 + 2*tq;
                    int kf0 = sh_meta[k0i] & 0xffff, kf1 = sh_meta[k0i+1] & 0xffff;
#pragma unroll
                    for (int mt=0; mt<2; mt++) {
                        float p0 = ex2(s[mt][nt][0] + rpbp[rb[mt][0]-kf0]);
                        float p1 = ex2(s[mt][nt][1] + rpbp[rb[mt][0]-kf1]);
                        float p2 = ex2(s[mt][nt][2] + rpbp[rb[mt][1]-kf0]);
                        float p3 = ex2(s[mt][nt][3] + rpbp[rb[mt][1]-kf1]);
                        psL[mt] += p0 + p1;
                        psH[mt] += p2 + p3;
                        pl[mt][nt] = pk(p0, p1);
                        ph[mt][nt] = pk(p2, p3);
                    }
                }
            } else {
#pragma unroll
                for (int nt=0; nt<4; nt++) {
                    int k0i = kb + nt*8 + 2*tq;
                    int me0 = sh_meta[k0i], me1 = sh_meta[k0i+1];
                    int kf0 = me0 & 0xffff, kr0 = me0 >> 16;
                    int kf1 = me1 & 0xffff, kr1 = me1 >> 16;
#pragma unroll
                    for (int mt=0; mt<2; mt++) {
                        float e0 = ex2(s[mt][nt][0] + rpbp[rb[mt][0]-kf0]);
                        float e1 = ex2(s[mt][nt][1] + rpbp[rb[mt][0]-kf1]);
                        float e2 = ex2(s[mt][nt][2] + rpbp[rb[mt][1]-kf0]);
                        float e3 = ex2(s[mt][nt][3] + rpbp[rb[mt][1]-kf1]);
                        float p0 = (kr0 == rid[mt][0]) ? e0 : 0.f;
                        float p1 = (kr1 == rid[mt][0]) ? e1 : 0.f;
                        float p2 = (kr0 == rid[mt][1]) ? e2 : 0.f;
                        float p3 = (kr1 == rid[mt][1]) ? e3 : 0.f;
                        psL[mt] += p0 + p1;
                        psH[mt] += p2 + p3;
                        pl[mt][nt] = pk(p0, p1);
                        ph[mt][nt] = pk(p2, p3);
                    }
                }
            }
#pragma unroll
            for (int ks = 0; ks < 2; ks++) {
                unsigned A0[4] = {pl[0][2*ks], ph[0][2*ks], pl[0][2*ks+1], ph[0][2*ks+1]};
                unsigned A1[4] = {pl[1][2*ks], ph[1][2*ks], pl[1][2*ks+1], ph[1][2*ks+1]};
#pragma unroll
                for (int nt=0; nt<4; nt++) {
                    unsigned B[2];
                    int vr = kc*16 + ks*8 + tq;
                    B[0]=sh_v[vr*40 + nt*8+tg];
                    B[1]=sh_v[(vr+4)*40 + nt*8+tg];
                    mma_bf16(o[0][nt], A0, B);
                    mma_bf16(o[1][nt], A1, B);
                }
            }
        }
#pragma unroll
        for (int mt=0; mt<2; mt++) {
            float sL = psL[mt], sH = psH[mt];
            sL += __shfl_xor_sync(0xffffffffu, sL, 1); sL += __shfl_xor_sync(0xffffffffu, sL, 2);
            sH += __shfl_xor_sync(0xffffffffu, sH, 1); sH += __shfl_xor_sync(0xffffffffu, sH, 2);
            float i0 = 1.f/sL, i1 = 1.f/sH;
#pragma unroll
            for (int ks = 0; ks < 2; ks++) {
                unsigned A[4] = {pk(o[mt][2*ks][0]*i0,   o[mt][2*ks][1]*i0),
                                 pk(o[mt][2*ks][2]*i1,   o[mt][2*ks][3]*i1),
                                 pk(o[mt][2*ks+1][0]*i0, o[mt][2*ks+1][1]*i0),
                                 pk(o[mt][2*ks+1][2]*i1, o[mt][2*ks+1][3]*i1)};
#pragma unroll
                for (int nt=0; nt<4; nt++) {
                    unsigned B[2];
                    B[0]=sh_rev[(hh*16 + 8*ks+tq)*40 + nt*8+tg];
                    B[1]=sh_rev[(hh*16 + 8*ks+tq+4)*40 + nt*8+tg];
                    mma_bf16(acc_rev[mt][nt], A, B);
                }
            }
        }
        if (hh < 7) { CPA_WAIT0; __syncthreads(); }
    }
    __syncthreads();

    // ---- residual + LN2 + lp1, written at un-shifted global positions ----
    unsigned* sh_a = sh_kT;
    int b = w >> 6, ww = w & 63;
    int wy = (ww >> 3)*16, wx = (ww & 7)*16;
    long tt0[2], tt1[2];
#pragma unroll
    for (int mt=0; mt<2; mt++) {
        int n0 = qb + mt*16 + tg;
        int y   = (wy + (n0 >> 4) + 8) & 127;
        int gx0 = (wx + tg + 8) & 127;
        int gx1 = (wx + tg + 16) & 127;
        long t0 = (long)b*16384 + (long)y*128 + gx0;
        long t1 = (long)b*16384 + (long)y*128 + gx1;
        tt0[mt] = t0; tt1[mt] = t1;
        float v0[4], v1[4], v2[4], v3[4];
#pragma unroll
        for (int nt=0; nt<4; nt++) {
            int col = nt*8 + 2*tq;
            float b0 = sh_f[col], b1v = sh_f[col+1];
            float2 x0 = *(const float2*)(x + t0*32 + col);
            float2 x1 = *(const float2*)(x + t1*32 + col);
            v0[nt]=acc_rev[mt][nt][0]+b0+x0.x; v1[nt]=acc_rev[mt][nt][1]+b1v+x0.y;
            v2[nt]=acc_rev[mt][nt][2]+b0+x1.x; v3[nt]=acc_rev[mt][nt][3]+b1v+x1.y;
            *(float2*)(g_xres + t0*32 + col) = make_float2(v0[nt], v1[nt]);
            *(float2*)(g_xres + t1*32 + col) = make_float2(v2[nt], v3[nt]);
        }
        float sL=0.f, qL=0.f, sH=0.f, qH=0.f;
#pragma unroll
        for (int nt=0; nt<4; nt++) {
            sL += v0[nt]+v1[nt]; qL += v0[nt]*v0[nt]+v1[nt]*v1[nt];
            sH += v2[nt]+v3[nt]; qH += v2[nt]*v2[nt]+v3[nt]*v3[nt];
        }
        sL += __shfl_xor_sync(0xffffffffu, sL, 1); sL += __shfl_xor_sync(0xffffffffu, sL, 2);
        qL += __shfl_xor_sync(0xffffffffu, qL, 1); qL += __shfl_xor_sync(0xffffffffu, qL, 2);
        sH += __shfl_xor_sync(0xffffffffu, sH, 1); sH += __shfl_xor_sync(0xffffffffu, sH, 2);
        qH += __shfl_xor_sync(0xffffffffu, qH, 1); qH += __shfl_xor_sync(0xffffffffu, qH, 2);
        float mL = sL*(1.f/32.f), mH = sH*(1.f/32.f);
        float rL = rsqrtf(qL*(1.f/32.f) - mL*mL + 1e-5f);
        float rH = rsqrtf(qH*(1.f/32.f) - mH*mH + 1e-5f);
#pragma unroll
        for (int nt=0; nt<4; nt++) {
            int col = nt*8 + 2*tq;
            float g0 = sh_f[32+col], g1 = sh_f[33+col], bt0 = sh_f[64+col], bt1 = sh_f[65+col];
            sh_a[n0*20 + nt*4+tq]     = pk((v0[nt]-mL)*rL*g0+bt0, (v1[nt]-mL)*rL*g1+bt1);
            sh_a[(n0+8)*20 + nt*4+tq] = pk((v2[nt]-mH)*rH*g0+bt0, (v3[nt]-mH)*rH*g1+bt1);
        }
    }
    __syncwarp();

#pragma unroll
    for (int mt=0; mt<2; mt++) {
        int n0 = qb + mt*16 + tg;
        long t0 = tt0[mt], t1 = tt1[mt];
#pragma unroll
        for (int h2 = 0; h2 < 2; h2++) {
            float acc2[8][4];
#pragma unroll
            for (int nt=0; nt<8; nt++)
#pragma unroll
                for (int r=0; r<4; r++) acc2[nt][r] = 0.f;
#pragma unroll
            for (int ks = 0; ks < 2; ks++) {
                int k2b = ks*8;
                unsigned A[4];
                A[0]=sh_a[n0*20 + k2b+tq];
                A[1]=sh_a[(n0+8)*20 + k2b+tq];
                A[2]=sh_a[n0*20 + k2b+tq+4];
                A[3]=sh_a[(n0+8)*20 + k2b+tq+4];
#pragma unroll
                for (int nt=0; nt<8; nt++) {
                    unsigned B[2];
                    B[0]=sh_w1[(k2b+tq)*136 + h2*64 + nt*8+tg];
                    B[1]=sh_w1[(k2b+tq+4)*136 + h2*64 + nt*8+tg];
                    mma_bf16(acc2[nt], A, B);
                }
            }
#pragma unroll
            for (int nt=0; nt<8; nt++) {
                int col = h2*64 + nt*8 + 2*tq;
                float b0 = sh_f[96+col], b1v = sh_f[97+col];
                g_y1[t0*64 + (col>>1)] = pk(gelu_exact(acc2[nt][0]+b0), gelu_exact(acc2[nt][1]+b1v));
                g_y1[t1*64 + (col>>1)] = pk(gelu_exact(acc2[nt][2]+b0), gelu_exact(acc2[nt][3]+b1v));
            }
        }
    }
}

// ============ K5: 3x3 conv implicit GEMM + fused lp2 + residual =========
// input tile pixel-major: [pix 324][c2 16 + pad 4] stride 20 (conflict-free)
#define CIS2 20
#define CONV_SMEM ((6480 + 19584 + 2560)*4)
__global__ void __launch_bounds__(256,2) k_conv(const float* __restrict__ cb,
                                                const float* __restrict__ b2,
                                                float* __restrict__ out) {
    extern __shared__ unsigned smu[];
    unsigned* sh_in = smu;               // 324*20
    unsigned* sh_w  = smu + 6480;        // [tap*16+c2][co 128] stride 136 (reused as sh_t)
    unsigned* sh_w2 = sh_w + 19584;      // 64*40
    int bz = blockIdx.x;
    int b = bz >> 7;
    int y0 = ((bz >> 3) & 15) * 8;
    int x0 = (bz & 7) * 16;
    int tid = threadIdx.x, lane = tid & 31, warp = tid >> 5;
    int tg = lane >> 2, tq = lane & 3;
    int wm = warp & 1, wn = warp >> 1;

    for (int j = tid; j < 640; j += 256) cpa16((uint4*)sh_w2 + j, (const uint4*)g_pw_w2 + j);
    CPA_COMMIT;

    float acc[4][4][4];
#pragma unroll
    for (int mt=0; mt<4; mt++)
#pragma unroll
        for (int nt=0; nt<4; nt++)
#pragma unroll
            for (int r=0; r<4; r++) acc[mt][nt][r] = 0.f;

    for (int ci0 = 0; ci0 < 128; ci0 += 32) {
        int c2b = ci0 >> 1;
        __syncthreads();
        // weights: 4608 x 16B async
        for (int j = tid; j < 4608; j += 256) {
            int row = j >> 5, q = j & 31;
            cpa16(sh_w + row*136 + q*4,
                  g_pw_cw + ((size_t)(row>>4)*64 + c2b + (row&15))*128 + q*4);
        }
        // input tile: pixel-major, 4 x cp.async(zfill) per pixel — fully async
        for (int j = tid; j < 1296; j += 256) {
            int pix = j >> 2, q = j & 3;
            int py = pix / 18, px = pix - py*18;
            int gy = y0 - 1 + py, gx = x0 - 1 + px;
            bool ok = ((unsigned)gy < 128u) && ((unsigned)gx < 128u);
            const unsigned* src = g_y1 +
                ((size_t)(b*16384 + (ok?gy:0)*128 + (ok?gx:0)))*64 + c2b + q*4;
            cpa16z(sh_in + pix*CIS2 + q*4, src, ok ? 16 : 0);
        }
        CPA_COMMIT;
        CPA_WAIT0;
        __syncthreads();
#pragma unroll
        for (int tap = 0; tap < 9; tap++) {
            int ky = tap / 3, kx = tap % 3;
#pragma unroll
            for (int ks = 0; ks < 2; ks++) {
                int k2b = ks*8;
                unsigned A[4][4];
#pragma unroll
                for (int mt=0; mt<4; mt++) {
                    int prow = (wm*4 + mt + ky)*18 + tg + kx;
                    A[mt][0]=sh_in[prow*CIS2 + k2b + tq];
                    A[mt][1]=sh_in[(prow+8)*CIS2 + k2b + tq];
                    A[mt][2]=sh_in[prow*CIS2 + k2b + tq + 4];
                    A[mt][3]=sh_in[(prow+8)*CIS2 + k2b + tq + 4];
                }
#pragma unroll
                for (int nt=0; nt<4; nt++) {
                    unsigned B[2];
                    B[0]=sh_w[(tap*16 + k2b+tq)*136 + wn*32 + nt*8+tg];
                    B[1]=sh_w[(tap*16 + k2b+tq+4)*136 + wn*32 + nt*8+tg];
#pragma unroll
                    for (int mt=0; mt<4; mt++) mma_bf16(acc[mt][nt], A[mt], B);
                }
            }
        }
    }
    __syncthreads();
    unsigned* sh_t = sh_w;  // [pix 128][k2 64] stride 68
#pragma unroll
    for (int mt=0; mt<4; mt++) {
        int pix0 = (wm*4 + mt)*16 + tg;
#pragma unroll
        for (int nt=0; nt<4; nt++) {
            int col = wn*32 + nt*8 + 2*tq;
            int k2 = col >> 1;
            float b0 = cb[col], b1 = cb[col+1];
            sh_t[pix0*68 + k2]     = pk(gelu_exact(acc[mt][nt][0]+b0), gelu_exact(acc[mt][nt][1]+b1));
            sh_t[(pix0+8)*68 + k2] = pk(gelu_exact(acc[mt][nt][2]+b0), gelu_exact(acc[mt][nt][3]+b1));
        }
    }
    __syncthreads();
    float acc3[4][4];
#pragma unroll
    for (int nt=0; nt<4; nt++)
#pragma unroll
        for (int r=0; r<4; r++) acc3[nt][r] = 0.f;
    int rr = warp*16 + tg;
#pragma unroll
    for (int ks = 0; ks < 8; ks++) {
        int k2b = ks*8;
        unsigned A[4];
        A[0]=sh_t[rr*68 + k2b+tq];
        A[1]=sh_t[(rr+8)*68 + k2b+tq];
        A[2]=sh_t[rr*68 + k2b+tq+4];
        A[3]=sh_t[(rr+8)*68 + k2b+tq+4];
#pragma unroll
        for (int nt=0; nt<4; nt++) {
            unsigned B[2];
            B[0]=sh_w2[(k2b+tq)*40 + nt*8+tg];
            B[1]=sh_w2[(k2b+tq+4)*40 + nt*8+tg];
            mma_bf16(acc3[nt], A, B);
        }
    }
    long t0 = (long)b*16384 + (long)(y0 + warp)*128 + x0 + tg;
    long t1 = t0 + 8;
#pragma unroll
    for (int nt=0; nt<4; nt++) {
        int col = nt*8 + 2*tq;
        float b0 = b2[col], b1 = b2[col+1];
        float2 x0v = *(const float2*)(g_xres + t0*32 + col);
        float2 x1v = *(const float2*)(g_xres + t1*32 + col);
        *(float2*)(out + t0*32 + col) =
            make_float2(gelu_exact(acc3[nt][0]+b0)+x0v.x, gelu_exact(acc3[nt][1]+b1)+x0v.y);
        *(float2*)(out + t1*32 + col) =
            make_float2(gelu_exact(acc3[nt][2]+b0)+x1v.x, gelu_exact(acc3[nt][3]+b1)+x1v.y);
    }
}

extern "C" void kernel_launch(void* const* d_in, const int* in_sizes, int n_in,
                              void* d_out, int out_size) {
    const float* x    = (const float*)d_in[0];
    const float* n1g  = (const float*)d_in[1];
    const float* n1b  = (const float*)d_in[2];
    const float* modw = (const float*)d_in[3];
    const float* qkvw = (const float*)d_in[4];
    const float* qkvb = (const float*)d_in[5];
    const float* rpbt = (const float*)d_in[6];
    const float* revw = (const float*)d_in[7];
    const float* revb = (const float*)d_in[8];
    const float* n2g  = (const float*)d_in[9];
    const float* n2b  = (const float*)d_in[10];
    const float* lp1w = (const float*)d_in[11];
    const float* lp1b = (const float*)d_in[12];
    const float* convw= (const float*)d_in[13];
    const float* convb= (const float*)d_in[14];
    const float* lp2w = (const float*)d_in[15];
    const float* lp2b = (const float*)d_in[16];
    float* out = (float*)d_out;

    cudaFuncSetAttribute(k_attn, cudaFuncAttributeMaxDynamicSharedMemorySize, ATTN_SMEM);
    cudaFuncSetAttribute(k_conv, cudaFuncAttributeMaxDynamicSharedMemorySize, CONV_SMEM);

    k_pack<<<288, 256>>>(qkvw, revw, lp1w, lp2w, convw, rpbt);
    k_attn<<<NWIN, 256, ATTN_SMEM>>>(x, n1g, n1b, modw, qkvb, revb, n2g, n2b, lp1b);
    k_conv<<<BQ * 16 * 8, 256, CONV_SMEM>>>(convb, lp2b, out);
}

// round 17
// speedup vs baseline: 1.5319x; 1.5319x over previous
#include <cuda_runtime.h>
#include <cuda_bf16.h>
#include <math.h>

#define BQ 8
#define NTOK 256
#define HH 8
#define CC 32
#define INNER 128
#define NWIN 512
#define NTOKENS (BQ*128*128)

__device__ float    g_xres[(size_t)NTOKENS*CC];
__device__ unsigned g_y1[(size_t)NTOKENS*64];
// packed weights (zero-init pads)
__device__ unsigned g_pw_qkv[8*16*104];
__device__ unsigned g_pw_rev[128*40];
__device__ unsigned g_pw_w1[16*136];
__device__ unsigned g_pw_w2[64*40];
__device__ unsigned g_pw_cw[9*64*128];
__device__ float    g_rpbp[8*964];    // pre-scaled by log2(e)

__device__ __forceinline__ float gelu_exact(float x) {
    return 0.5f * x * (1.0f + erff(x * 0.70710678118654752440f));
}
__device__ __forceinline__ float ex2(float x) {
    float r; asm("ex2.approx.f32 %0, %1;" : "=f"(r) : "f"(x));
    return r;
}
__device__ __forceinline__ unsigned pk(float a, float b) {
    __nv_bfloat162 t = __floats2bfloat162_rn(a, b);
    return *reinterpret_cast<unsigned*>(&t);
}
__device__ __forceinline__ void mma_bf16(float* c, const unsigned* a, const unsigned* b) {
    asm volatile("mma.sync.aligned.m16n8k16.row.col.f32.bf16.bf16.f32 "
        "{%0,%1,%2,%3},{%4,%5,%6,%7},{%8,%9},{%0,%1,%2,%3};"
        : "+f"(c[0]), "+f"(c[1]), "+f"(c[2]), "+f"(c[3])
        : "r"(a[0]), "r"(a[1]), "r"(a[2]), "r"(a[3]), "r"(b[0]), "r"(b[1]));
}
__device__ __forceinline__ void cpa16(void* dst, const void* src) {
    unsigned d = (unsigned)__cvta_generic_to_shared(dst);
    asm volatile("cp.async.cg.shared.global [%0], [%1], 16;" :: "r"(d), "l"(src));
}
#define CPA_COMMIT asm volatile("cp.async.commit_group;" ::: "memory")
#define CPA_WAIT0  asm volatile("cp.async.wait_group 0;" ::: "memory")

// ============ K0: one-time weight packing ================================
__global__ void k_pack(const float* __restrict__ qkvw, const float* __restrict__ revw,
                       const float* __restrict__ w1, const float* __restrict__ w2,
                       const float* __restrict__ cw, const float* __restrict__ rpbt) {
    int i = blockIdx.x * 256 + threadIdx.x;
    if (i < 73728) {
        int tap = i >> 13, r = i & 8191;
        int c2 = r >> 7, co = r & 127;
        g_pw_cw[i] = pk(cw[((size_t)tap*128 + 2*c2)*128 + co],
                        cw[((size_t)tap*128 + 2*c2 + 1)*128 + co]);
    }
    if (i < 12288) {
        int hh = i / 1536, r = i % 1536;
        int c2 = r / 96, col = r % 96;
        int gcol = (col >> 5)*256 + hh*32 + (col & 31);
        g_pw_qkv[(hh*16 + c2)*104 + col] = pk(qkvw[2*c2*768 + gcol], qkvw[(2*c2+1)*768 + gcol]);
    }
    if (i < 7712) {
        int hh = i / 964, j = i % 964;
        g_rpbp[hh*964 + j] = (j < 961) ? rpbt[j*8 + hh] * 1.4426950408889634f : 0.f;
    }
    if (i < 4096) {
        int k2 = i >> 5, n = i & 31;
        g_pw_rev[k2*40 + n] = pk(revw[2*k2*32 + n], revw[(2*k2+1)*32 + n]);
    }
    if (i < 2048) {
        int c2 = i >> 7, n = i & 127;
        g_pw_w1[c2*136 + n] = pk(w1[2*c2*128 + n], w1[(2*c2+1)*128 + n]);
    }
    if (i < 2048) {
        int k2 = i >> 5, n = i & 31;
        g_pw_w2[k2*40 + n] = pk(w2[2*k2*32 + n], w2[(2*k2+1)*32 + n]);
    }
}

// ============ K2: window megakernel: LN1 + QKV + attn(8h) + rev + LN2 + lp1
#define ATTN_SMEM (23144*4)
__global__ void __launch_bounds__(256,2) k_attn(const float* __restrict__ x,
        const float* __restrict__ n1g, const float* __restrict__ n1b,
        const float* __restrict__ modw,
        const float* __restrict__ qkvb, const float* __restrict__ revb,
        const float* __restrict__ n2g, const float* __restrict__ n2b,
        const float* __restrict__ bb1) {
    extern __shared__ unsigned smu[];
    unsigned* sh_kT  = smu;                 // 4224 (start: sh_h overlay; end: sh_a)
    unsigned* sh_v   = smu + 4224;          // 5120
    unsigned* sh_wq  = smu + 9344;          // 2x1664 double buffer
    unsigned* sh_rev = smu + 12672;         // 5120
    unsigned* sh_w1  = smu + 17792;         // 2176
    float* sh_rpb    = (float*)(smu + 19968);  // 2x964 double buffer
    int*   sh_meta   = (int*)(smu + 21896);    // 256
    float* sh_ball   = (float*)(smu + 22152);  // 768
    float* sh_f      = (float*)(smu + 22920);  // 224

    int w = blockIdx.x;
    int tid = threadIdx.x, lane = tid & 31, warp = tid >> 5;
    int tg = lane >> 2, tq = lane & 3;
    int qb = warp * 32;
    bool uni = (((w & 63) >> 3) < 7) && ((w & 7) < 7);

    // ---- one-time staging via cp.async (pure copies) ----
    for (int j = tid; j < 1280; j += 256) cpa16((uint4*)sh_rev + j, (const uint4*)g_pw_rev + j);
    for (int j = tid; j < 544; j += 256)  cpa16((uint4*)sh_w1 + j, (const uint4*)g_pw_w1 + j);
    for (int j = tid; j < 416; j += 256)  cpa16((uint4*)sh_wq + j, (const uint4*)g_pw_qkv + j);
    for (int j = tid; j < 241; j += 256)  cpa16((uint4*)sh_rpb + j, (const uint4*)g_rpbp + j);
    CPA_COMMIT;
    for (int j = tid; j < 768; j += 256)  sh_ball[j] = qkvb[j];
    if (tid < 32) { sh_f[tid] = revb[tid]; sh_f[32+tid] = n2g[tid]; sh_f[64+tid] = n2b[tid]; }
    if (tid < 128) sh_f[96+tid] = bb1[tid];
    {
        int n = tid, ww = w & 63;
        int ry = (ww>>3)*16 + (n>>4), rx = (ww&7)*16 + (n&15);
        int hr = ry < 112 ? 0 : (ry < 120 ? 1 : 2);
        int wr = rx < 112 ? 0 : (rx < 120 ? 1 : 2);
        sh_meta[n] = ((n>>4)*31 + (n&15)) | ((hr*3+wr) << 16);
    }

    // ---- LN1 + shift + modulator -> sh_h (transient overlay on kT) ----
    unsigned* sh_h = sh_kT;
    {
        int n = tid, b = w >> 6, ww = w & 63;
        int ry = (ww>>3)*16 + (n>>4), rx = (ww&7)*16 + (n&15);
        int y = (ry + 8) & 127, xx = (rx + 8) & 127;
        const float* xp = x + ((size_t)b*16384 + (size_t)y*128 + xx)*CC;
        float v[CC];
#pragma unroll
        for (int i = 0; i < 8; i++) {
            float4 t = ((const float4*)xp)[i];
            v[4*i]=t.x; v[4*i+1]=t.y; v[4*i+2]=t.z; v[4*i+3]=t.w;
        }
        float mean = 0.f;
#pragma unroll
        for (int c = 0; c < CC; c++) mean += v[c];
        mean *= (1.0f/CC);
        float var = 0.f;
#pragma unroll
        for (int c = 0; c < CC; c++) { float d = v[c]-mean; var += d*d; }
        float rstd = rsqrtf(var*(1.0f/CC) + 1e-5f);
        const float4* mp = (const float4*)(modw + n*CC);
#pragma unroll
        for (int i = 0; i < 8; i++) {
            float4 m = mp[i];
            int c = 4*i;
            sh_h[n*20 + 2*i]   = pk((v[c+0]-mean)*rstd*n1g[c+0]+n1b[c+0]+m.x,
                                    (v[c+1]-mean)*rstd*n1g[c+1]+n1b[c+1]+m.y);
            sh_h[n*20 + 2*i+1] = pk((v[c+2]-mean)*rstd*n1g[c+2]+n1b[c+2]+m.z,
                                    (v[c+3]-mean)*rstd*n1g[c+3]+n1b[c+3]+m.w);
        }
    }
    CPA_WAIT0;
    __syncthreads();

    unsigned ha[2][8];
#pragma unroll
    for (int mt = 0; mt < 2; mt++) {
        int r = qb + mt*16 + tg;
        ha[mt][0]=sh_h[r*20+tq];        ha[mt][1]=sh_h[(r+8)*20+tq];
        ha[mt][2]=sh_h[r*20+tq+4];      ha[mt][3]=sh_h[(r+8)*20+tq+4];
        ha[mt][4]=sh_h[r*20+tq+8];      ha[mt][5]=sh_h[(r+8)*20+tq+8];
        ha[mt][6]=sh_h[r*20+tq+12];     ha[mt][7]=sh_h[(r+8)*20+tq+12];
    }
    int rb[2][2], rid[2][2];
#pragma unroll
    for (int mt=0; mt<2; mt++)
#pragma unroll
        for (int h=0; h<2; h++) {
            int q = qb + mt*16 + tg + 8*h;
            rb[mt][h] = ((q>>4)+15)*31 + ((q&15)+15);
            rid[mt][h] = sh_meta[q] >> 16;
        }
    __syncthreads();

    float acc_rev[2][4][4];
#pragma unroll
    for (int mt=0; mt<2; mt++)
#pragma unroll
        for (int nt=0; nt<4; nt++)
#pragma unroll
            for (int r=0; r<4; r++) acc_rev[mt][nt][r] = 0.f;

    // ================= head loop =================
    for (int hh = 0; hh < 8; hh++) {
        int p = hh & 1;
        const unsigned* wqp = sh_wq + p*1664;
        const float* rpbp = sh_rpb + p*964;

        unsigned qrl[2][4], qrh[2][4];
        __nv_bfloat16* vb = (__nv_bfloat16*)sh_v;
#pragma unroll
        for (int sec = 0; sec < 3; sec++) {
            float acc[2][4][4];
#pragma unroll
            for (int mt=0; mt<2; mt++)
#pragma unroll
                for (int nt=0; nt<4; nt++)
#pragma unroll
                    for (int r=0; r<4; r++) acc[mt][nt][r] = 0.f;
#pragma unroll
            for (int ks = 0; ks < 2; ks++) {
#pragma unroll
                for (int nt=0; nt<4; nt++) {
                    unsigned B[2];
                    B[0]=wqp[(8*ks+tq)*104 + sec*32 + nt*8+tg];
                    B[1]=wqp[(8*ks+tq+4)*104 + sec*32 + nt*8+tg];
                    mma_bf16(acc[0][nt], &ha[0][ks*4], B);
                    mma_bf16(acc[1][nt], &ha[1][ks*4], B);
                }
            }
#pragma unroll
            for (int mt=0; mt<2; mt++)
#pragma unroll
            for (int nt=0; nt<4; nt++) {
                int col = nt*8 + 2*tq;
                int r0 = qb + mt*16 + tg;
                float bb0 = sh_ball[sec*256 + hh*32 + col];
                float bb1v = sh_ball[sec*256 + hh*32 + col + 1];
                float v0=acc[mt][nt][0]+bb0, v1=acc[mt][nt][1]+bb1v;
                float v2=acc[mt][nt][2]+bb0, v3=acc[mt][nt][3]+bb1v;
                if (sec == 0) {
                    const float SC = 0.25508694038098612f;  // 1/sqrt(32)*log2(e)
                    qrl[mt][nt] = pk(v0*SC, v1*SC);
                    qrh[mt][nt] = pk(v2*SC, v3*SC);
                } else if (sec == 1) {
                    sh_kT[(col>>1)*264 + r0]   = pk(v0, v1);
                    sh_kT[(col>>1)*264 + r0+8] = pk(v2, v3);
                } else {
                    int r1 = r0 + 8, par = r0 & 1;
                    vb[(r0>>1)*80 + col*2     + par] = __float2bfloat16(v0);
                    vb[(r0>>1)*80 + (col+1)*2 + par] = __float2bfloat16(v1);
                    vb[(r1>>1)*80 + col*2     + par] = __float2bfloat16(v2);
                    vb[(r1>>1)*80 + (col+1)*2 + par] = __float2bfloat16(v3);
                }
            }
        }
        // ---- prefetch next head (async; completes during flash+rev) ----
        if (hh < 7) {
            const uint4* src = (const uint4*)(g_pw_qkv + (hh+1)*1664);
            uint4* dst = (uint4*)(sh_wq + (1-p)*1664);
            for (int j = tid; j < 416; j += 256) cpa16(dst + j, src + j);
            const uint4* rs = (const uint4*)(g_rpbp + (hh+1)*964);
            uint4* rd = (uint4*)(sh_rpb + (1-p)*964);
            for (int j = tid; j < 241; j += 256) cpa16(rd + j, rs + j);
            CPA_COMMIT;
        }
        __syncthreads();   // kT/V visible

        float psL[2] = {0.f,0.f}, psH[2] = {0.f,0.f};
        float o[2][4][4];
#pragma unroll
        for (int mt=0; mt<2; mt++)
#pragma unroll
            for (int nt=0; nt<4; nt++)
#pragma unroll
                for (int r=0; r<4; r++) o[mt][nt][r] = 0.f;

        for (int kc = 0; kc < 8; kc++) {
            int kb = kc * 32;
            float s[2][4][4];
#pragma unroll
            for (int mt=0; mt<2; mt++)
#pragma unroll
                for (int nt=0; nt<4; nt++)
#pragma unroll
                    for (int r=0; r<4; r++) s[mt][nt][r] = 0.f;
#pragma unroll
            for (int ks = 0; ks < 2; ks++) {
                unsigned A0[4] = {qrl[0][2*ks], qrh[0][2*ks], qrl[0][2*ks+1], qrh[0][2*ks+1]};
                unsigned A1[4] = {qrl[1][2*ks], qrh[1][2*ks], qrl[1][2*ks+1], qrh[1][2*ks+1]};
#pragma unroll
                for (int nt=0; nt<4; nt++) {
                    unsigned B[2];
                    int key = kb + nt*8 + tg;
                    B[0]=sh_kT[(8*ks+tq)*264 + key];
                    B[1]=sh_kT[(8*ks+tq+4)*264 + key];
                    mma_bf16(s[0][nt], A0, B);
                    mma_bf16(s[1][nt], A1, B);
                }
            }
            unsigned pl[2][4], ph[2][4];
            if (uni) {
#pragma unroll
                for (int nt=0; nt<4; nt++) {
                    int k0i = kb + nt*8 + 2*tq;
                    int kf0 = sh_meta[k0i] & 0xffff, kf1 = sh_meta[k0i+1] & 0xffff;
#pragma unroll
                    for (int mt=0; mt<2; mt++) {
                        float p0 = ex2(s[mt][nt][0] + rpbp[rb[mt][0]-kf0]);
                        float p1 = ex2(s[mt][nt][1] + rpbp[rb[mt][0]-kf1]);
                        float p2 = ex2(s[mt][nt][2] + rpbp[rb[mt][1]-kf0]);
                        float p3 = ex2(s[mt][nt][3] + rpbp[rb[mt][1]-kf1]);
                        psL[mt] += p0 + p1;
                        psH[mt] += p2 + p3;
                        pl[mt][nt] = pk(p0, p1);
                        ph[mt][nt] = pk(p2, p3);
                    }
                }
            } else {
#pragma unroll
                for (int nt=0; nt<4; nt++) {
                    int k0i = kb + nt*8 + 2*tq;
                    int me0 = sh_meta[k0i], me1 = sh_meta[k0i+1];
                    int kf0 = me0 & 0xffff, kr0 = me0 >> 16;
                    int kf1 = me1 & 0xffff, kr1 = me1 >> 16;
#pragma unroll
                    for (int mt=0; mt<2; mt++) {
                        float e0 = ex2(s[mt][nt][0] + rpbp[rb[mt][0]-kf0]);
                        float e1 = ex2(s[mt][nt][1] + rpbp[rb[mt][0]-kf1]);
                        float e2 = ex2(s[mt][nt][2] + rpbp[rb[mt][1]-kf0]);
                        float e3 = ex2(s[mt][nt][3] + rpbp[rb[mt][1]-kf1]);
                        float p0 = (kr0 == rid[mt][0]) ? e0 : 0.f;
                        float p1 = (kr1 == rid[mt][0]) ? e1 : 0.f;
                        float p2 = (kr0 == rid[mt][1]) ? e2 : 0.f;
                        float p3 = (kr1 == rid[mt][1]) ? e3 : 0.f;
                        psL[mt] += p0 + p1;
                        psH[mt] += p2 + p3;
                        pl[mt][nt] = pk(p0, p1);
                        ph[mt][nt] = pk(p2, p3);
                    }
                }
            }
#pragma unroll
            for (int ks = 0; ks < 2; ks++) {
                unsigned A0[4] = {pl[0][2*ks], ph[0][2*ks], pl[0][2*ks+1], ph[0][2*ks+1]};
                unsigned A1[4] = {pl[1][2*ks], ph[1][2*ks], pl[1][2*ks+1], ph[1][2*ks+1]};
#pragma unroll
                for (int nt=0; nt<4; nt++) {
                    unsigned B[2];
                    int vr = kc*16 + ks*8 + tq;
                    B[0]=sh_v[vr*40 + nt*8+tg];
                    B[1]=sh_v[(vr+4)*40 + nt*8+tg];
                    mma_bf16(o[0][nt], A0, B);
                    mma_bf16(o[1][nt], A1, B);
                }
            }
        }
#pragma unroll
        for (int mt=0; mt<2; mt++) {
            float sL = psL[mt], sH = psH[mt];
            sL += __shfl_xor_sync(0xffffffffu, sL, 1); sL += __shfl_xor_sync(0xffffffffu, sL, 2);
            sH += __shfl_xor_sync(0xffffffffu, sH, 1); sH += __shfl_xor_sync(0xffffffffu, sH, 2);
            float i0 = 1.f/sL, i1 = 1.f/sH;
#pragma unroll
            for (int ks = 0; ks < 2; ks++) {
                unsigned A[4] = {pk(o[mt][2*ks][0]*i0,   o[mt][2*ks][1]*i0),
                                 pk(o[mt][2*ks][2]*i1,   o[mt][2*ks][3]*i1),
                                 pk(o[mt][2*ks+1][0]*i0, o[mt][2*ks+1][1]*i0),
                                 pk(o[mt][2*ks+1][2]*i1, o[mt][2*ks+1][3]*i1)};
#pragma unroll
                for (int nt=0; nt<4; nt++) {
                    unsigned B[2];
                    B[0]=sh_rev[(hh*16 + 8*ks+tq)*40 + nt*8+tg];
                    B[1]=sh_rev[(hh*16 + 8*ks+tq+4)*40 + nt*8+tg];
                    mma_bf16(acc_rev[mt][nt], A, B);
                }
            }
        }
        if (hh < 7) { CPA_WAIT0; __syncthreads(); }
    }
    __syncthreads();

    // ---- residual + LN2 + lp1, written at un-shifted global positions ----
    unsigned* sh_a = sh_kT;
    int b = w >> 6, ww = w & 63;
    int wy = (ww >> 3)*16, wx = (ww & 7)*16;
    long tt0[2], tt1[2];
#pragma unroll
    for (int mt=0; mt<2; mt++) {
        int n0 = qb + mt*16 + tg;
        int y   = (wy + (n0 >> 4) + 8) & 127;
        int gx0 = (wx + tg + 8) & 127;
        int gx1 = (wx + tg + 16) & 127;
        long t0 = (long)b*16384 + (long)y*128 + gx0;
        long t1 = (long)b*16384 + (long)y*128 + gx1;
        tt0[mt] = t0; tt1[mt] = t1;
        float v0[4], v1[4], v2[4], v3[4];
#pragma unroll
        for (int nt=0; nt<4; nt++) {
            int col = nt*8 + 2*tq;
            float b0 = sh_f[col], b1v = sh_f[col+1];
            float2 x0 = *(const float2*)(x + t0*32 + col);
            float2 x1 = *(const float2*)(x + t1*32 + col);
            v0[nt]=acc_rev[mt][nt][0]+b0+x0.x; v1[nt]=acc_rev[mt][nt][1]+b1v+x0.y;
            v2[nt]=acc_rev[mt][nt][2]+b0+x1.x; v3[nt]=acc_rev[mt][nt][3]+b1v+x1.y;
            *(float2*)(g_xres + t0*32 + col) = make_float2(v0[nt], v1[nt]);
            *(float2*)(g_xres + t1*32 + col) = make_float2(v2[nt], v3[nt]);
        }
        float sL=0.f, qL=0.f, sH=0.f, qH=0.f;
#pragma unroll
        for (int nt=0; nt<4; nt++) {
            sL += v0[nt]+v1[nt]; qL += v0[nt]*v0[nt]+v1[nt]*v1[nt];
            sH += v2[nt]+v3[nt]; qH += v2[nt]*v2[nt]+v3[nt]*v3[nt];
        }
        sL += __shfl_xor_sync(0xffffffffu, sL, 1); sL += __shfl_xor_sync(0xffffffffu, sL, 2);
        qL += __shfl_xor_sync(0xffffffffu, qL, 1); qL += __shfl_xor_sync(0xffffffffu, qL, 2);
        sH += __shfl_xor_sync(0xffffffffu, sH, 1); sH += __shfl_xor_sync(0xffffffffu, sH, 2);
        qH += __shfl_xor_sync(0xffffffffu, qH, 1); qH += __shfl_xor_sync(0xffffffffu, qH, 2);
        float mL = sL*(1.f/32.f), mH = sH*(1.f/32.f);
        float rL = rsqrtf(qL*(1.f/32.f) - mL*mL + 1e-5f);
        float rH = rsqrtf(qH*(1.f/32.f) - mH*mH + 1e-5f);
#pragma unroll
        for (int nt=0; nt<4; nt++) {
            int col = nt*8 + 2*tq;
            float g0 = sh_f[32+col], g1 = sh_f[33+col], bt0 = sh_f[64+col], bt1 = sh_f[65+col];
            sh_a[n0*20 + nt*4+tq]     = pk((v0[nt]-mL)*rL*g0+bt0, (v1[nt]-mL)*rL*g1+bt1);
            sh_a[(n0+8)*20 + nt*4+tq] = pk((v2[nt]-mH)*rH*g0+bt0, (v3[nt]-mH)*rH*g1+bt1);
        }
    }
    __syncwarp();

#pragma unroll
    for (int mt=0; mt<2; mt++) {
        int n0 = qb + mt*16 + tg;
        long t0 = tt0[mt], t1 = tt1[mt];
#pragma unroll
        for (int h2 = 0; h2 < 2; h2++) {
            float acc2[8][4];
#pragma unroll
            for (int nt=0; nt<8; nt++)
#pragma unroll
                for (int r=0; r<4; r++) acc2[nt][r] = 0.f;
#pragma unroll
            for (int ks = 0; ks < 2; ks++) {
                int k2b = ks*8;
                unsigned A[4];
                A[0]=sh_a[n0*20 + k2b+tq];
                A[1]=sh_a[(n0+8)*20 + k2b+tq];
                A[2]=sh_a[n0*20 + k2b+tq+4];
                A[3]=sh_a[(n0+8)*20 + k2b+tq+4];
#pragma unroll
                for (int nt=0; nt<8; nt++) {
                    unsigned B[2];
                    B[0]=sh_w1[(k2b+tq)*136 + h2*64 + nt*8+tg];
                    B[1]=sh_w1[(k2b+tq+4)*136 + h2*64 + nt*8+tg];
                    mma_bf16(acc2[nt], A, B);
                }
            }
#pragma unroll
            for (int nt=0; nt<8; nt++) {
                int col = h2*64 + nt*8 + 2*tq;
                float b0 = sh_f[96+col], b1v = sh_f[97+col];
                g_y1[t0*64 + (col>>1)] = pk(gelu_exact(acc2[nt][0]+b0), gelu_exact(acc2[nt][1]+b1v));
                g_y1[t1*64 + (col>>1)] = pk(gelu_exact(acc2[nt][2]+b0), gelu_exact(acc2[nt][3]+b1v));
            }
        }
    }
}

// ============ K5: 3x3 conv implicit GEMM + fused lp2 + residual =========
// input pixel-major: [pix 324][c2 16 + pad 4] stride 20 (banks 20*tg+tq distinct)
// sh_w2 loaded AFTER mainloop into dead sh_in region -> SMEM = 104256 B (2 blocks/SM)
#define CIS2 20
#define CONV_SMEM ((6480 + 19584)*4)
__global__ void __launch_bounds__(256,2) k_conv(const float* __restrict__ cb,
                                                const float* __restrict__ b2,
                                                float* __restrict__ out) {
    extern __shared__ unsigned smu[];
    unsigned* sh_in = smu;               // 324*20 (reused as sh_w2 in epilogue)
    unsigned* sh_w  = smu + 6480;        // [tap*16+c2][co 128] stride 136 (reused as sh_t)
    int bz = blockIdx.x;
    int b = bz >> 7;
    int y0 = ((bz >> 3) & 15) * 8;
    int x0 = (bz & 7) * 16;
    int tid = threadIdx.x, lane = tid & 31, warp = tid >> 5;
    int tg = lane >> 2, tq = lane & 3;
    int wm = warp & 1, wn = warp >> 1;

    float acc[4][4][4];
#pragma unroll
    for (int mt=0; mt<4; mt++)
#pragma unroll
        for (int nt=0; nt<4; nt++)
#pragma unroll
            for (int r=0; r<4; r++) acc[mt][nt][r] = 0.f;

    for (int ci0 = 0; ci0 < 128; ci0 += 32) {
        int c2b = ci0 >> 1;
        __syncthreads();
        // weights: 4608 x 16B async
        for (int j = tid; j < 4608; j += 256) {
            int row = j >> 5, q = j & 31;
            cpa16(sh_w + row*136 + q*4,
                  g_pw_cw + ((size_t)(row>>4)*64 + c2b + (row&15))*128 + q*4);
        }
        // input tile: pixel-major, 4 cp.async per interior pixel; zeros for OOB
        for (int j = tid; j < 1296; j += 256) {
            int pix = j >> 2, q = j & 3;
            int py = pix / 18, px = pix - py*18;
            int gy = y0 - 1 + py, gx = x0 - 1 + px;
            if (((unsigned)gy < 128u) && ((unsigned)gx < 128u)) {
                cpa16(sh_in + pix*CIS2 + q*4,
                      g_y1 + ((size_t)(b*16384 + gy*128 + gx))*64 + c2b + q*4);
            } else {
                *(uint4*)(sh_in + pix*CIS2 + q*4) = make_uint4(0,0,0,0);
            }
        }
        CPA_COMMIT;
        CPA_WAIT0;
        __syncthreads();
#pragma unroll
        for (int tap = 0; tap < 9; tap++) {
            int ky = tap / 3, kx = tap % 3;
#pragma unroll
            for (int ks = 0; ks < 2; ks++) {
                int k2b = ks*8;
                unsigned A[4][4];
#pragma unroll
                for (int mt=0; mt<4; mt++) {
                    int prow = (wm*4 + mt + ky)*18 + tg + kx;
                    A[mt][0]=sh_in[prow*CIS2 + k2b + tq];
                    A[mt][1]=sh_in[(prow+8)*CIS2 + k2b + tq];
                    A[mt][2]=sh_in[prow*CIS2 + k2b + tq + 4];
                    A[mt][3]=sh_in[(prow+8)*CIS2 + k2b + tq + 4];
                }
#pragma unroll
                for (int nt=0; nt<4; nt++) {
                    unsigned B[2];
                    B[0]=sh_w[(tap*16 + k2b+tq)*136 + wn*32 + nt*8+tg];
                    B[1]=sh_w[(tap*16 + k2b+tq+4)*136 + wn*32 + nt*8+tg];
#pragma unroll
                    for (int mt=0; mt<4; mt++) mma_bf16(acc[mt][nt], A[mt], B);
                }
            }
        }
    }
    __syncthreads();   // mainloop reads of sh_in / sh_w done
    unsigned* sh_w2 = sh_in;   // 2560 words into dead input region
    for (int j = tid; j < 640; j += 256) cpa16((uint4*)sh_w2 + j, (const uint4*)g_pw_w2 + j);
    CPA_COMMIT;
    unsigned* sh_t = sh_w;  // [pix 128][k2 64] stride 68
#pragma unroll
    for (int mt=0; mt<4; mt++) {
        int pix0 = (wm*4 + mt)*16 + tg;
#pragma unroll
        for (int nt=0; nt<4; nt++) {
            int col = wn*32 + nt*8 + 2*tq;
            int k2 = col >> 1;
            float b0 = cb[col], b1 = cb[col+1];
            sh_t[pix0*68 + k2]     = pk(gelu_exact(acc[mt][nt][0]+b0), gelu_exact(acc[mt][nt][1]+b1));
            sh_t[(pix0+8)*68 + k2] = pk(gelu_exact(acc[mt][nt][2]+b0), gelu_exact(acc[mt][nt][3]+b1));
        }
    }
    CPA_WAIT0;
    __syncthreads();
    float acc3[4][4];
#pragma unroll
    for (int nt=0; nt<4; nt++)
#pragma unroll
        for (int r=0; r<4; r++) acc3[nt][r] = 0.f;
    int rr = warp*16 + tg;
#pragma unroll
    for (int ks = 0; ks < 8; ks++) {
        int k2b = ks*8;
        unsigned A[4];
        A[0]=sh_t[rr*68 + k2b+tq];
        A[1]=sh_t[(rr+8)*68 + k2b+tq];
        A[2]=sh_t[rr*68 + k2b+tq+4];
        A[3]=sh_t[(rr+8)*68 + k2b+tq+4];
#pragma unroll
        for (int nt=0; nt<4; nt++) {
            unsigned B[2];
            B[0]=sh_w2[(k2b+tq)*40 + nt*8+tg];
            B[1]=sh_w2[(k2b+tq+4)*40 + nt*8+tg];
            mma_bf16(acc3[nt], A, B);
        }
    }
    long t0 = (long)b*16384 + (long)(y0 + warp)*128 + x0 + tg;
    long t1 = t0 + 8;
#pragma unroll
    for (int nt=0; nt<4; nt++) {
        int col = nt*8 + 2*tq;
        float b0 = b2[col], b1 = b2[col+1];
        float2 x0v = *(const float2*)(g_xres + t0*32 + col);
        float2 x1v = *(const float2*)(g_xres + t1*32 + col);
        *(float2*)(out + t0*32 + col) =
            make_float2(gelu_exact(acc3[nt][0]+b0)+x0v.x, gelu_exact(acc3[nt][1]+b1)+x0v.y);
        *(float2*)(out + t1*32 + col) =
            make_float2(gelu_exact(acc3[nt][2]+b0)+x1v.x, gelu_exact(acc3[nt][3]+b1)+x1v.y);
    }
}

extern "C" void kernel_launch(void* const* d_in, const int* in_sizes, int n_in,
                              void* d_out, int out_size) {
    const float* x    = (const float*)d_in[0];
    const float* n1g  = (const float*)d_in[1];
    const float* n1b  = (const float*)d_in[2];
    const float* modw = (const float*)d_in[3];
    const float* qkvw = (const float*)d_in[4];
    const float* qkvb = (const float*)d_in[5];
    const float* rpbt = (const float*)d_in[6];
    const float* revw = (const float*)d_in[7];
    const float* revb = (const float*)d_in[8];
    const float* n2g  = (const float*)d_in[9];
    const float* n2b  = (const float*)d_in[10];
    const float* lp1w = (const float*)d_in[11];
    const float* lp1b = (const float*)d_in[12];
    const float* convw= (const float*)d_in[13];
    const float* convb= (const float*)d_in[14];
    const float* lp2w = (const float*)d_in[15];
    const float* lp2b = (const float*)d_in[16];
    float* out = (float*)d_out;

    cudaFuncSetAttribute(k_attn, cudaFuncAttributeMaxDynamicSharedMemorySize, ATTN_SMEM);
    cudaFuncSetAttribute(k_conv, cudaFuncAttributeMaxDynamicSharedMemorySize, CONV_SMEM);

    k_pack<<<288, 256>>>(qkvw, revw, lp1w, lp2w, convw, rpbt);
    k_attn<<<NWIN, 256, ATTN_SMEM>>>(x, n1g, n1b, modw, qkvb, revb, n2g, n2b, lp1b);
    k_conv<<<BQ * 16 * 8, 256, CONV_SMEM>>>(convb, lp2b, out);
}